// round 7
// baseline (speedup 1.0000x reference)
#include <cuda_runtime.h>
#include <math.h>

#define N_NODES 50000
#define D_IN 128
#define MAX_SRC 2048
#define BM_WORDS 1568          // ceil(50000/32)
#define NW 8                   // worker blocks for the MLP tail
#define STASH_CAP 22528        // u16 entries (44KB)
#define SMEM_BYTES 98304       // 96KB dynamic

// smem offsets (worker blocks)
#define OFF_CONV 0             // 128*32 f  = 16KB
#define OFF_FC1  16384         // 256*32 f  = 32KB
#define OFF_FC2  49152         // 256*32 f  = 32KB
#define OFF_MU   81920         // 8*256 f   =  8KB (block 0, transposed)
#define OFF_SCR4 90112         // 4KB float4 scratch (sred / cred)
#define OFF_XIN  94208         // 256 f
#define OFF_AGG  95232         // 128 f
#define OFF_MISC 95744         // few floats

// persistent device scratch (zero-initialized; kernel leaves it zeroed)
__device__ int g_deg[N_NODES];
__device__ unsigned g_bitmap[BM_WORDS];
__device__ int g_srcs[MAX_SRC];
__device__ int g_nsrc;
__device__ unsigned g_arrive;
__device__ volatile unsigned g_epoch;
__device__ unsigned g_wb_arrive;
__device__ volatile unsigned g_wb_epoch;
// inter-worker staging (fully overwritten each replay)
__device__ float4 g_aggp[NW][32];
__device__ float4 g_x1v[64];
__device__ float4 g_y1v[64];
__device__ float4 g_y2v[64];
__device__ float g_part[2][NW][2];

// ---------------------------------------------------------------------------
__device__ __forceinline__ void gbar() {
    __syncthreads();
    if (threadIdx.x == 0) {
        __threadfence();
        unsigned e = g_epoch;
        if (atomicAdd(&g_arrive, 1u) == gridDim.x - 1) {
            g_arrive = 0;
            __threadfence();
            g_epoch = e + 1;
        } else {
            while (g_epoch == e) __nanosleep(20);
        }
        __threadfence();
    }
    __syncthreads();
}

// 8-worker mini-barrier; wait_=false -> arrive only
__device__ __forceinline__ void wbar(bool wait_) {
    __syncthreads();
    if (threadIdx.x == 0) {
        __threadfence();
        unsigned e = g_wb_epoch;
        if (atomicAdd(&g_wb_arrive, 1u) == NW - 1) {
            g_wb_arrive = 0;
            __threadfence();
            g_wb_epoch = e + 1;
        } else if (wait_) {
            while (g_wb_epoch == e) __nanosleep(20);
        }
        __threadfence();
    }
    __syncthreads();
}

// ---------------------------------------------------------------------------
__global__ void __launch_bounds__(256, 1) k_fused(
    const float* __restrict__ state,
    const void*  __restrict__ edges,
    const void*  __restrict__ agent_ptr,
    const float* __restrict__ conv_w, const float* __restrict__ conv_b,
    const float* __restrict__ fc1_w,  const float* __restrict__ fc1_b,
    const float* __restrict__ ln1_w,  const float* __restrict__ ln1_b,
    const float* __restrict__ fc2_w,  const float* __restrict__ fc2_b,
    const float* __restrict__ ln2_w,  const float* __restrict__ ln2_b,
    const float* __restrict__ mu_w,   const float* __restrict__ mu_b,
    float* __restrict__ out, long long E)
{
    extern __shared__ __align__(16) unsigned char sbuf[];
    unsigned short* stash = (unsigned short*)sbuf;

    const int t = threadIdx.x;
    const int w = blockIdx.x;
    const bool worker = (w < NW);

    // ---- local decode: edge dtype + agent ---------------------------------
    int is64 = 1;
    {
        const int* wd = (const int*)edges;
        #pragma unroll
        for (int j = 0; j < 16; j++)
            if (wd[2 * j + 1] != 0) { is64 = 0; break; }
    }
    int agent = *(const int*)agent_ptr;
    if (agent < 0 || agent >= N_NODES) agent = (int)(*(const float*)agent_ptr);

    // ---- workers: preload weight slices into smem (overlaps with scan) ----
    if (worker) {
        const int of4 = t & 7, kg = t >> 3;
        float4* wcv = (float4*)(sbuf + OFF_CONV);
        #pragma unroll
        for (int k = kg; k < 128; k += 32)
            wcv[k * 8 + of4] = __ldg((const float4*)(conv_w + (size_t)k * 256 + w * 32) + of4);
        float4* wf1 = (float4*)(sbuf + OFF_FC1);
        #pragma unroll
        for (int k = kg; k < 256; k += 32)
            wf1[k * 8 + of4] = __ldg((const float4*)(fc1_w + (size_t)k * 256 + w * 32) + of4);
        float4* wf2 = (float4*)(sbuf + OFF_FC2);
        #pragma unroll
        for (int k = kg; k < 256; k += 32)
            wf2[k * 8 + of4] = __ldg((const float4*)(fc2_w + (size_t)k * 256 + w * 32) + of4);
        if (w == 0) {
            float* wmuT = (float*)(sbuf + OFF_MU);     // [8][256] transposed
            #pragma unroll
            for (int o = 0; o < 8; o++)
                wmuT[o * 256 + t] = __ldg(&mu_w[t * 8 + o]);
        }
    }

    // ---- P1: scan this block's dst chunk ----------------------------------
    long long chunk = (E + gridDim.x - 1) / gridDim.x;
    chunk = (chunk + 3) & ~3LL;
    const long long start = (long long)w * chunk;
    const long long end   = min(start + chunk, E);
    const int clen = (int)max(0LL, end - start);
    const bool dostash = !worker && (chunk <= STASH_CAP);

    if (is64) {
        const long long* src = (const long long*)edges;
        const long long* dst = src + E;
        const bool vec = ((((size_t)(dst + start)) & 15) == 0);
        if (vec) {
            const int vlim = clen & ~1;
            for (int j = t * 2; j + 1 < vlim; j += 512) {
                longlong2 v = *(const longlong2*)(dst + start + j);
                if (dostash) {
                    unsigned pack = (unsigned)(unsigned short)v.x |
                                    ((unsigned)(unsigned short)v.y << 16);
                    *(unsigned*)(stash + j) = pack;
                }
                if ((int)v.x == agent) {
                    int p = atomicAdd(&g_nsrc, 1);
                    if (p < MAX_SRC) {
                        int s = (int)src[start + j];
                        g_srcs[p] = s;
                        atomicOr(&g_bitmap[s >> 5], 1u << (s & 31));
                    }
                }
                if ((int)v.y == agent) {
                    int p = atomicAdd(&g_nsrc, 1);
                    if (p < MAX_SRC) {
                        int s = (int)src[start + j + 1];
                        g_srcs[p] = s;
                        atomicOr(&g_bitmap[s >> 5], 1u << (s & 31));
                    }
                }
            }
            for (int k = vlim + t; k < clen; k += 256) {
                int d = (int)dst[start + k];
                if (dostash) stash[k] = (unsigned short)d;
                if (d == agent) {
                    int p = atomicAdd(&g_nsrc, 1);
                    if (p < MAX_SRC) {
                        int s = (int)src[start + k];
                        g_srcs[p] = s;
                        atomicOr(&g_bitmap[s >> 5], 1u << (s & 31));
                    }
                }
            }
        } else {
            for (int j = t; j < clen; j += 256) {
                int d = (int)dst[start + j];
                if (dostash) stash[j] = (unsigned short)d;
                if (d == agent) {
                    int p = atomicAdd(&g_nsrc, 1);
                    if (p < MAX_SRC) {
                        int s = (int)src[start + j];
                        g_srcs[p] = s;
                        atomicOr(&g_bitmap[s >> 5], 1u << (s & 31));
                    }
                }
            }
        }
    } else {
        const int* src = (const int*)edges;
        const int* dst = src + E;
        const bool vec = ((((size_t)(dst + start)) & 15) == 0);
        if (vec) {
            const int vlim = clen & ~3;
            for (int j = t * 4; j + 3 < vlim; j += 1024) {
                int4 v = *(const int4*)(dst + start + j);
                if (dostash) {
                    *(unsigned*)(stash + j) = (unsigned)(unsigned short)v.x |
                                              ((unsigned)(unsigned short)v.y << 16);
                    *(unsigned*)(stash + j + 2) = (unsigned)(unsigned short)v.z |
                                                  ((unsigned)(unsigned short)v.w << 16);
                }
                int dd[4] = {v.x, v.y, v.z, v.w};
                #pragma unroll
                for (int q = 0; q < 4; q++) {
                    if (dd[q] == agent) {
                        int p = atomicAdd(&g_nsrc, 1);
                        if (p < MAX_SRC) {
                            int s = src[start + j + q];
                            g_srcs[p] = s;
                            atomicOr(&g_bitmap[s >> 5], 1u << (s & 31));
                        }
                    }
                }
            }
            for (int k = (clen & ~3) + t; k < clen; k += 256) {
                int d = dst[start + k];
                if (dostash) stash[k] = (unsigned short)d;
                if (d == agent) {
                    int p = atomicAdd(&g_nsrc, 1);
                    if (p < MAX_SRC) {
                        int s = src[start + k];
                        g_srcs[p] = s;
                        atomicOr(&g_bitmap[s >> 5], 1u << (s & 31));
                    }
                }
            }
        } else {
            for (int j = t; j < clen; j += 256) {
                int d = dst[start + j];
                if (dostash) stash[j] = (unsigned short)d;
                if (d == agent) {
                    int p = atomicAdd(&g_nsrc, 1);
                    if (p < MAX_SRC) {
                        int s = src[start + j];
                        g_srcs[p] = s;
                        atomicOr(&g_bitmap[s >> 5], 1u << (s & 31));
                    }
                }
            }
        }
    }
    gbar();

    // ---- P2: filtered degree histogram ------------------------------------
    if (dostash) {
        for (int j = t; j < clen; j += 256) {
            int d = stash[j];
            unsigned wd = __ldg(&g_bitmap[d >> 5]);
            if ((wd >> (d & 31)) & 1u) atomicAdd(&g_deg[d], 1);
        }
    } else {
        const long long* dst64 = (const long long*)edges + E;
        const int*       dst32 = (const int*)edges + E;
        for (int j = t; j < clen; j += 256) {
            int d = is64 ? (int)dst64[start + j] : dst32[start + j];
            unsigned wd = __ldg(&g_bitmap[d >> 5]);
            if ((wd >> (d & 31)) & 1u) atomicAdd(&g_deg[d], 1);
        }
    }
    gbar();

    if (!worker) return;

    // ================= distributed MLP on blocks 0..7 ======================
    float4* scr4 = (float4*)(sbuf + OFF_SCR4);
    float*  xin  = (float*)(sbuf + OFF_XIN);
    float*  agg  = (float*)(sbuf + OFF_AGG);
    float*  misc = (float*)(sbuf + OFF_MISC);

    const int lane = t & 31, wp = t >> 5;
    const int of4 = t & 7, kg = t >> 3;
    const int n = min(g_nsrc, MAX_SRC);
    const float dinv_a = rsqrtf((float)(g_nsrc + 1));

    // ---- stage A: aggregation partials (global warp gw handles m=gw,+64) --
    {
        float4 a = make_float4(0.f, 0.f, 0.f, 0.f);
        for (int m = w * 8 + wp; m < n; m += 64) {
            int s = g_srcs[m];
            float nm = rsqrtf((float)(g_deg[s] + 1)) * dinv_a;
            float4 v = __ldg((const float4*)(state + (size_t)s * D_IN) + lane);
            a.x += nm * v.x; a.y += nm * v.y; a.z += nm * v.z; a.w += nm * v.w;
        }
        scr4[wp * 32 + lane] = a;
        __syncthreads();
        if (t < 32) {
            float4 s4 = scr4[t];
            #pragma unroll
            for (int j = 1; j < 8; j++) {
                float4 b = scr4[j * 32 + t];
                s4.x += b.x; s4.y += b.y; s4.z += b.z; s4.w += b.w;
            }
            if (w == 0) {
                float4 av = __ldg((const float4*)(state + (size_t)agent * D_IN) + t);
                float c = dinv_a * dinv_a;
                s4.x += c * av.x; s4.y += c * av.y; s4.z += c * av.z; s4.w += c * av.w;
            }
            g_aggp[w][t] = s4;
        }
    }
    wbar(true);

    // ---- stage B: conv GEMV (32 outputs/block) + relu ----------------------
    {
        if (t < 32) {
            float4 s4 = g_aggp[0][t];
            #pragma unroll
            for (int j = 1; j < 8; j++) {
                float4 b = g_aggp[j][t];
                s4.x += b.x; s4.y += b.y; s4.z += b.z; s4.w += b.w;
            }
            ((float4*)agg)[t] = s4;
        }
        __syncthreads();
        const float4* wcv = (const float4*)(sbuf + OFF_CONV);
        float4 acc = make_float4(0.f, 0.f, 0.f, 0.f);
        #pragma unroll
        for (int i = 0; i < 4; i++) {
            int k = kg * 4 + i;
            float xs = agg[k];
            float4 wv = wcv[k * 8 + of4];
            acc.x += xs * wv.x; acc.y += xs * wv.y; acc.z += xs * wv.z; acc.w += xs * wv.w;
        }
        scr4[kg * 8 + of4] = acc;
        __syncthreads();
        if (t < 8) {
            float4 r = scr4[t];
            #pragma unroll
            for (int j = 1; j < 32; j++) {
                float4 b = scr4[j * 8 + t];
                r.x += b.x; r.y += b.y; r.z += b.z; r.w += b.w;
            }
            float4 bb = __ldg((const float4*)conv_b + w * 8 + t);
            r.x = fmaxf(r.x + bb.x, 0.f); r.y = fmaxf(r.y + bb.y, 0.f);
            r.z = fmaxf(r.z + bb.z, 0.f); r.w = fmaxf(r.w + bb.w, 0.f);
            g_x1v[w * 8 + t] = r;
        }
    }
    wbar(true);

    // ---- stage C: fc1 GEMV + LN partials -----------------------------------
    {
        if (t < 64) ((float4*)xin)[t] = g_x1v[t];
        __syncthreads();
        const float4* wf1 = (const float4*)(sbuf + OFF_FC1);
        float4 acc = make_float4(0.f, 0.f, 0.f, 0.f);
        #pragma unroll
        for (int i = 0; i < 8; i++) {
            int k = kg * 8 + i;
            float xs = xin[k];
            float4 wv = wf1[k * 8 + of4];
            acc.x += xs * wv.x; acc.y += xs * wv.y; acc.z += xs * wv.z; acc.w += xs * wv.w;
        }
        scr4[kg * 8 + of4] = acc;
        __syncthreads();
        if (t < 8) {
            float4 r = scr4[t];
            #pragma unroll
            for (int j = 1; j < 32; j++) {
                float4 b = scr4[j * 8 + t];
                r.x += b.x; r.y += b.y; r.z += b.z; r.w += b.w;
            }
            float4 bb = __ldg((const float4*)fc1_b + w * 8 + t);
            r.x += bb.x; r.y += bb.y; r.z += bb.z; r.w += bb.w;
            g_y1v[w * 8 + t] = r;
            float s = r.x + r.y + r.z + r.w;
            float q = r.x * r.x + r.y * r.y + r.z * r.z + r.w * r.w;
            #pragma unroll
            for (int off = 4; off > 0; off >>= 1) {
                s += __shfl_down_sync(0xffu, s, off, 8);
                q += __shfl_down_sync(0xffu, q, off, 8);
            }
            if (t == 0) { g_part[0][w][0] = s; g_part[0][w][1] = q; }
        }
    }
    wbar(true);

    // ---- stage D: LN1+relu inline, fc2 GEMV + LN partials ------------------
    {
        if (t == 0) {
            float s = 0.f, q = 0.f;
            #pragma unroll
            for (int j = 0; j < NW; j++) { s += g_part[0][j][0]; q += g_part[0][j][1]; }
            float mean = s * (1.0f / 256.0f);
            float var  = q * (1.0f / 256.0f) - mean * mean;
            misc[0] = mean; misc[1] = rsqrtf(var + 1e-5f);
        }
        __syncthreads();
        if (t < 64) {
            float mean = misc[0], is = misc[1];
            float4 y  = g_y1v[t];
            float4 lw = __ldg((const float4*)ln1_w + t);
            float4 lb = __ldg((const float4*)ln1_b + t);
            float4 r;
            r.x = fmaxf((y.x - mean) * is * lw.x + lb.x, 0.f);
            r.y = fmaxf((y.y - mean) * is * lw.y + lb.y, 0.f);
            r.z = fmaxf((y.z - mean) * is * lw.z + lb.z, 0.f);
            r.w = fmaxf((y.w - mean) * is * lw.w + lb.w, 0.f);
            ((float4*)xin)[t] = r;
        }
        __syncthreads();
        const float4* wf2 = (const float4*)(sbuf + OFF_FC2);
        float4 acc = make_float4(0.f, 0.f, 0.f, 0.f);
        #pragma unroll
        for (int i = 0; i < 8; i++) {
            int k = kg * 8 + i;
            float xs = xin[k];
            float4 wv = wf2[k * 8 + of4];
            acc.x += xs * wv.x; acc.y += xs * wv.y; acc.z += xs * wv.z; acc.w += xs * wv.w;
        }
        scr4[kg * 8 + of4] = acc;
        __syncthreads();
        if (t < 8) {
            float4 r = scr4[t];
            #pragma unroll
            for (int j = 1; j < 32; j++) {
                float4 b = scr4[j * 8 + t];
                r.x += b.x; r.y += b.y; r.z += b.z; r.w += b.w;
            }
            float4 bb = __ldg((const float4*)fc2_b + w * 8 + t);
            r.x += bb.x; r.y += bb.y; r.z += bb.z; r.w += bb.w;
            g_y2v[w * 8 + t] = r;
            float s = r.x + r.y + r.z + r.w;
            float q = r.x * r.x + r.y * r.y + r.z * r.z + r.w * r.w;
            #pragma unroll
            for (int off = 4; off > 0; off >>= 1) {
                s += __shfl_down_sync(0xffu, s, off, 8);
                q += __shfl_down_sync(0xffu, q, off, 8);
            }
            if (t == 0) { g_part[1][w][0] = s; g_part[1][w][1] = q; }
        }
    }
    wbar(w == 0);          // workers 1..7 arrive and exit; block 0 waits
    if (w != 0) return;

    // ---- stage E (block 0): LN2+relu, mu head, sigmoid, cleanup ------------
    {
        if (t == 0) {
            float s = 0.f, q = 0.f;
            #pragma unroll
            for (int j = 0; j < NW; j++) { s += g_part[1][j][0]; q += g_part[1][j][1]; }
            float mean = s * (1.0f / 256.0f);
            float var  = q * (1.0f / 256.0f) - mean * mean;
            misc[2] = mean; misc[3] = rsqrtf(var + 1e-5f);
        }
        __syncthreads();
        if (t < 64) {
            float mean = misc[2], is = misc[3];
            float4 y  = g_y2v[t];
            float4 lw = __ldg((const float4*)ln2_w + t);
            float4 lb = __ldg((const float4*)ln2_b + t);
            float4 r;
            r.x = fmaxf((y.x - mean) * is * lw.x + lb.x, 0.f);
            r.y = fmaxf((y.y - mean) * is * lw.y + lb.y, 0.f);
            r.z = fmaxf((y.z - mean) * is * lw.z + lb.z, 0.f);
            r.w = fmaxf((y.w - mean) * is * lw.w + lb.w, 0.f);
            ((float4*)xin)[t] = r;
        }
        __syncthreads();
        const float* wmuT = (const float*)(sbuf + OFF_MU);
        float acc = 0.f;
        #pragma unroll
        for (int k = lane; k < 256; k += 32) acc += xin[k] * wmuT[wp * 256 + k];
        #pragma unroll
        for (int off = 16; off > 0; off >>= 1)
            acc += __shfl_down_sync(0xffffffffu, acc, off);
        if (lane == 0) {
            float z = acc + mu_b[wp];
            out[wp] = 1.0f / (1.0f + expf(-z));
        }
        __syncthreads();

        // cleanup: reset only touched global state (replay-clean)
        int nc = min(g_nsrc, MAX_SRC);
        for (int m = t; m < nc; m += 256) {
            int s = g_srcs[m];
            g_bitmap[s >> 5] = 0;
            g_deg[s] = 0;
        }
        if (t == 0) {
            g_deg[agent] = 0;
            g_nsrc = 0;
        }
    }
}

// ---------------------------------------------------------------------------
extern "C" void kernel_launch(void* const* d_in, const int* in_sizes, int n_in,
                              void* d_out, int out_size) {
    const float* state  = (const float*)d_in[0];
    const void*  edges  = d_in[1];
    const void*  agent  = d_in[2];
    const float* conv_w = (const float*)d_in[3];
    const float* conv_b = (const float*)d_in[4];
    const float* fc1_w  = (const float*)d_in[5];
    const float* fc1_b  = (const float*)d_in[6];
    const float* ln1_w  = (const float*)d_in[7];
    const float* ln1_b  = (const float*)d_in[8];
    const float* fc2_w  = (const float*)d_in[9];
    const float* fc2_b  = (const float*)d_in[10];
    const float* ln2_w  = (const float*)d_in[11];
    const float* ln2_b  = (const float*)d_in[12];
    const float* mu_w   = (const float*)d_in[13];
    const float* mu_b   = (const float*)d_in[14];

    long long E = (long long)in_sizes[1] / 2;

    int dev = 0, sms = 0;
    cudaGetDevice(&dev);
    cudaDeviceGetAttribute(&sms, cudaDevAttrMultiProcessorCount, dev);
    if (sms <= 0) sms = 64;

    cudaFuncSetAttribute(k_fused, cudaFuncAttributeMaxDynamicSharedMemorySize,
                         SMEM_BYTES);

    k_fused<<<sms, 256, SMEM_BYTES>>>(state, edges, agent, conv_w, conv_b,
                                      fc1_w, fc1_b, ln1_w, ln1_b,
                                      fc2_w, fc2_b, ln2_w, ln2_b,
                                      mu_w, mu_b, (float*)d_out, E);
}

// round 8
// speedup vs baseline: 1.4923x; 1.4923x over previous
#include <cuda_runtime.h>
#include <math.h>

#define N_NODES 50000
#define D_IN 128
#define MAX_SRC 2048
#define SH_SRC 1024
#define BM_WORDS 1568          // ceil(50000/32)
#define NW 8                   // worker blocks for distributed MLP tail
#define STASH_CAP 22528        // u16 entries (44KB)

// persistent device scratch (zero-initialized; kernel leaves it zeroed)
__device__ int g_deg[N_NODES];
__device__ unsigned g_bitmap[BM_WORDS];
__device__ int g_srcs[MAX_SRC];
__device__ int g_nsrc;
__device__ unsigned g_arrive;
__device__ volatile unsigned g_epoch;
__device__ unsigned g_wb_arrive;
__device__ volatile unsigned g_wb_epoch;
// inter-worker staging (fully overwritten each replay)
__device__ float4 g_y1v[64];
__device__ float4 g_y2v[64];
__device__ float g_part[2][NW][2];

// ---------------------------------------------------------------------------
__device__ __forceinline__ void gbar() {
    __syncthreads();
    if (threadIdx.x == 0) {
        __threadfence();
        unsigned e = g_epoch;
        if (atomicAdd(&g_arrive, 1u) == gridDim.x - 1) {
            g_arrive = 0;
            __threadfence();
            g_epoch = e + 1;
        } else {
            while (g_epoch == e) __nanosleep(20);
        }
        __threadfence();
    }
    __syncthreads();
}

// 8-worker mini-barrier; wait_=false -> arrive only
__device__ __forceinline__ void wbar(bool wait_) {
    __syncthreads();
    if (threadIdx.x == 0) {
        __threadfence();
        unsigned e = g_wb_epoch;
        if (atomicAdd(&g_wb_arrive, 1u) == NW - 1) {
            g_wb_arrive = 0;
            __threadfence();
            g_wb_epoch = e + 1;
        } else if (wait_) {
            while (g_wb_epoch == e) __nanosleep(20);
        }
        __threadfence();
    }
    __syncthreads();
}

// ---------------------------------------------------------------------------
__global__ void __launch_bounds__(256, 1) k_fused(
    const float* __restrict__ state,
    const void*  __restrict__ edges,
    const void*  __restrict__ agent_ptr,
    const float* __restrict__ conv_w, const float* __restrict__ conv_b,
    const float* __restrict__ fc1_w,  const float* __restrict__ fc1_b,
    const float* __restrict__ ln1_w,  const float* __restrict__ ln1_b,
    const float* __restrict__ fc2_w,  const float* __restrict__ fc2_b,
    const float* __restrict__ ln2_w,  const float* __restrict__ ln2_b,
    const float* __restrict__ mu_w,   const float* __restrict__ mu_b,
    float* __restrict__ out, long long E)
{
    __shared__ __align__(16) unsigned char sbuf[STASH_CAP * 2];
    unsigned short* stash = (unsigned short*)sbuf;

    const int t = threadIdx.x;
    const int w = blockIdx.x;

    // ---- local decode: edge dtype + agent ---------------------------------
    int is64 = 1;
    {
        const int* wd = (const int*)edges;
        #pragma unroll
        for (int j = 0; j < 16; j++)
            if (wd[2 * j + 1] != 0) { is64 = 0; break; }
    }
    int agent = *(const int*)agent_ptr;
    if (agent < 0 || agent >= N_NODES) agent = (int)(*(const float*)agent_ptr);

    // ---- P1: scan this block's dst chunk; stash u16; collect srcs+bitmap --
    long long chunk = (E + gridDim.x - 1) / gridDim.x;
    chunk = (chunk + 3) & ~3LL;
    const long long start = (long long)w * chunk;
    const long long end   = min(start + chunk, E);
    const int clen = (int)max(0LL, end - start);
    const bool fits = (chunk <= STASH_CAP);

    if (is64) {
        const long long* src = (const long long*)edges;
        const long long* dst = src + E;
        const bool vec = fits && ((((size_t)(dst + start)) & 15) == 0);
        if (vec) {
            const int vlim = clen & ~1;
            for (int j = t * 2; j + 1 < vlim; j += 512) {
                longlong2 v = *(const longlong2*)(dst + start + j);
                unsigned pack = (unsigned)(unsigned short)v.x |
                                ((unsigned)(unsigned short)v.y << 16);
                *(unsigned*)(stash + j) = pack;
                if ((int)v.x == agent) {
                    int p = atomicAdd(&g_nsrc, 1);
                    if (p < MAX_SRC) {
                        int s = (int)src[start + j];
                        g_srcs[p] = s;
                        atomicOr(&g_bitmap[s >> 5], 1u << (s & 31));
                    }
                }
                if ((int)v.y == agent) {
                    int p = atomicAdd(&g_nsrc, 1);
                    if (p < MAX_SRC) {
                        int s = (int)src[start + j + 1];
                        g_srcs[p] = s;
                        atomicOr(&g_bitmap[s >> 5], 1u << (s & 31));
                    }
                }
            }
            for (int k = vlim + t; k < clen; k += 256) {
                int d = (int)dst[start + k];
                stash[k] = (unsigned short)d;
                if (d == agent) {
                    int p = atomicAdd(&g_nsrc, 1);
                    if (p < MAX_SRC) {
                        int s = (int)src[start + k];
                        g_srcs[p] = s;
                        atomicOr(&g_bitmap[s >> 5], 1u << (s & 31));
                    }
                }
            }
        } else {
            for (int j = t; j < clen; j += 256) {
                int d = (int)dst[start + j];
                if (fits) stash[j] = (unsigned short)d;
                if (d == agent) {
                    int p = atomicAdd(&g_nsrc, 1);
                    if (p < MAX_SRC) {
                        int s = (int)src[start + j];
                        g_srcs[p] = s;
                        atomicOr(&g_bitmap[s >> 5], 1u << (s & 31));
                    }
                }
            }
        }
    } else {
        const int* src = (const int*)edges;
        const int* dst = src + E;
        const bool vec = fits && ((((size_t)(dst + start)) & 15) == 0);
        if (vec) {
            const int vlim = clen & ~3;
            for (int j = t * 4; j + 3 < vlim; j += 1024) {
                int4 v = *(const int4*)(dst + start + j);
                *(unsigned*)(stash + j)     = (unsigned)(unsigned short)v.x |
                                              ((unsigned)(unsigned short)v.y << 16);
                *(unsigned*)(stash + j + 2) = (unsigned)(unsigned short)v.z |
                                              ((unsigned)(unsigned short)v.w << 16);
                int dd[4] = {v.x, v.y, v.z, v.w};
                #pragma unroll
                for (int q = 0; q < 4; q++) {
                    if (dd[q] == agent) {
                        int p = atomicAdd(&g_nsrc, 1);
                        if (p < MAX_SRC) {
                            int s = src[start + j + q];
                            g_srcs[p] = s;
                            atomicOr(&g_bitmap[s >> 5], 1u << (s & 31));
                        }
                    }
                }
            }
            for (int k = vlim + t; k < clen; k += 256) {
                int d = dst[start + k];
                stash[k] = (unsigned short)d;
                if (d == agent) {
                    int p = atomicAdd(&g_nsrc, 1);
                    if (p < MAX_SRC) {
                        int s = src[start + k];
                        g_srcs[p] = s;
                        atomicOr(&g_bitmap[s >> 5], 1u << (s & 31));
                    }
                }
            }
        } else {
            for (int j = t; j < clen; j += 256) {
                int d = dst[start + j];
                if (fits) stash[j] = (unsigned short)d;
                if (d == agent) {
                    int p = atomicAdd(&g_nsrc, 1);
                    if (p < MAX_SRC) {
                        int s = src[start + j];
                        g_srcs[p] = s;
                        atomicOr(&g_bitmap[s >> 5], 1u << (s & 31));
                    }
                }
            }
        }
    }
    gbar();

    // ---- P2: filtered degree histogram ------------------------------------
    if (fits) {
        for (int j = t; j < clen; j += 256) {
            int d = stash[j];
            unsigned wd = __ldg(&g_bitmap[d >> 5]);
            if ((wd >> (d & 31)) & 1u) atomicAdd(&g_deg[d], 1);
        }
    } else {
        const long long* dst64 = (const long long*)edges + E;
        const int*       dst32 = (const int*)edges + E;
        for (int j = t; j < clen; j += 256) {
            int d = is64 ? (int)dst64[start + j] : dst32[start + j];
            unsigned wd = __ldg(&g_bitmap[d >> 5]);
            if ((wd >> (d & 31)) & 1u) atomicAdd(&g_deg[d], 1);
        }
    }
    gbar();

    if (w >= NW) return;

    // ================= distributed MLP on blocks 0..7 ======================
    // smem overlay on the (no longer needed) stash
    float*  agg   = (float*)(sbuf);                 // 128 f   [0,512)
    float*  xv    = (float*)(sbuf + 512);           // 256 f   [512,1536)
    float4* sred  = (float4*)(sbuf + 1536);         // 8*32 f4 [1536,5632)
    float4* cred  = (float4*)(sbuf + 5632);         // 4*64 f4 [5632,9728)  (also 32*8 f4 for fc)
    float*  misc  = (float*)(sbuf + 9728);          // few floats
    int*    ssrc  = (int*)(sbuf + 10240);           // 1024 i
    float*  snorm = (float*)(sbuf + 14336);         // 1024 f

    const int lane = t & 31, wp = t >> 5;
    const int n = min(g_nsrc, SH_SRC);
    const float dinv_a = rsqrtf((float)(g_nsrc + 1));

    __syncthreads();   // stash -> MLP scratch reuse
    for (int m = t; m < n; m += 256) {
        int s = g_srcs[m];
        ssrc[m]  = s;
        snorm[m] = rsqrtf((float)(g_deg[s] + 1)) * dinv_a;
    }
    __syncthreads();

    // ---- agg (redundant on each worker): warp wp takes m = wp, wp+8, ...
    {
        float4 a = make_float4(0.f, 0.f, 0.f, 0.f);
        for (int m = wp; m < n; m += 8) {
            const float4* row = (const float4*)(state + (size_t)ssrc[m] * D_IN);
            float4 v = __ldg(&row[lane]);
            float nm = snorm[m];
            a.x += nm * v.x; a.y += nm * v.y; a.z += nm * v.z; a.w += nm * v.w;
        }
        sred[wp * 32 + lane] = a;
        __syncthreads();
        if (t < 32) {
            float4 s4 = sred[t];
            #pragma unroll
            for (int j = 1; j < 8; j++) {
                float4 b = sred[j * 32 + t];
                s4.x += b.x; s4.y += b.y; s4.z += b.z; s4.w += b.w;
            }
            const float4* arow = (const float4*)(state + (size_t)agent * D_IN);
            float4 av = __ldg(&arow[t]);
            float c = dinv_a * dinv_a;
            s4.x += c * av.x; s4.y += c * av.y; s4.z += c * av.z; s4.w += c * av.w;
            ((float4*)agg)[t] = s4;
        }
        __syncthreads();
    }

    const int og = t & 63, sl = t >> 6;
    const int of4 = t & 7, kg = t >> 3;

    // ---- conv GEMV full (redundant per worker), 4-wide staging -------------
    {
        float4 acc = make_float4(0.f, 0.f, 0.f, 0.f);
        const int kb = sl * 32;
        #pragma unroll
        for (int kk = 0; kk < 32; kk += 4) {
            float4 wv[4];
            #pragma unroll
            for (int j = 0; j < 4; j++)
                wv[j] = __ldg((const float4*)(conv_w + (size_t)(kb + kk + j) * 256) + og);
            #pragma unroll
            for (int j = 0; j < 4; j++) {
                float xs = agg[kb + kk + j];
                acc.x += xs * wv[j].x; acc.y += xs * wv[j].y;
                acc.z += xs * wv[j].z; acc.w += xs * wv[j].w;
            }
        }
        cred[sl * 64 + og] = acc;
        __syncthreads();
        if (t < 64) {
            float4 r = cred[t], b1 = cred[64 + t], b2 = cred[128 + t], b3 = cred[192 + t];
            r.x += b1.x + b2.x + b3.x; r.y += b1.y + b2.y + b3.y;
            r.z += b1.z + b2.z + b3.z; r.w += b1.w + b2.w + b3.w;
            float4 bb = __ldg((const float4*)conv_b + t);
            r.x = fmaxf(r.x + bb.x, 0.f); r.y = fmaxf(r.y + bb.y, 0.f);
            r.z = fmaxf(r.z + bb.z, 0.f); r.w = fmaxf(r.w + bb.w, 0.f);
            ((float4*)xv)[t] = r;
        }
        __syncthreads();
    }

    // ---- fc1 slice (32 outputs at columns w*32..w*32+31) -------------------
    {
        float4 acc = make_float4(0.f, 0.f, 0.f, 0.f);
        #pragma unroll
        for (int i = 0; i < 8; i++) {
            int k = kg * 8 + i;
            float xs = xv[k];
            float4 wv = __ldg((const float4*)(fc1_w + (size_t)k * 256 + w * 32) + of4);
            acc.x += xs * wv.x; acc.y += xs * wv.y; acc.z += xs * wv.z; acc.w += xs * wv.w;
        }
        cred[kg * 8 + of4] = acc;
        __syncthreads();
        if (t < 8) {
            float4 r = cred[t];
            #pragma unroll
            for (int j = 1; j < 32; j++) {
                float4 b = cred[j * 8 + t];
                r.x += b.x; r.y += b.y; r.z += b.z; r.w += b.w;
            }
            float4 bb = __ldg((const float4*)fc1_b + w * 8 + t);
            r.x += bb.x; r.y += bb.y; r.z += bb.z; r.w += bb.w;
            g_y1v[w * 8 + t] = r;
            float s = r.x + r.y + r.z + r.w;
            float q = r.x * r.x + r.y * r.y + r.z * r.z + r.w * r.w;
            #pragma unroll
            for (int off = 4; off > 0; off >>= 1) {
                s += __shfl_down_sync(0xffu, s, off, 8);
                q += __shfl_down_sync(0xffu, q, off, 8);
            }
            if (t == 0) { g_part[0][w][0] = s; g_part[0][w][1] = q; }
        }
    }
    wbar(true);

    // ---- LN1 + relu (redundant), fc2 slice ---------------------------------
    {
        if (t == 0) {
            float s = 0.f, q = 0.f;
            #pragma unroll
            for (int j = 0; j < NW; j++) { s += g_part[0][j][0]; q += g_part[0][j][1]; }
            float mean = s * (1.0f / 256.0f);
            float var  = q * (1.0f / 256.0f) - mean * mean;
            misc[0] = mean; misc[1] = rsqrtf(var + 1e-5f);
        }
        __syncthreads();
        if (t < 64) {
            float mean = misc[0], is = misc[1];
            float4 y  = g_y1v[t];
            float4 lw = __ldg((const float4*)ln1_w + t);
            float4 lb = __ldg((const float4*)ln1_b + t);
            float4 r;
            r.x = fmaxf((y.x - mean) * is * lw.x + lb.x, 0.f);
            r.y = fmaxf((y.y - mean) * is * lw.y + lb.y, 0.f);
            r.z = fmaxf((y.z - mean) * is * lw.z + lb.z, 0.f);
            r.w = fmaxf((y.w - mean) * is * lw.w + lb.w, 0.f);
            ((float4*)xv)[t] = r;
        }
        __syncthreads();

        float4 acc = make_float4(0.f, 0.f, 0.f, 0.f);
        #pragma unroll
        for (int i = 0; i < 8; i++) {
            int k = kg * 8 + i;
            float xs = xv[k];
            float4 wv = __ldg((const float4*)(fc2_w + (size_t)k * 256 + w * 32) + of4);
            acc.x += xs * wv.x; acc.y += xs * wv.y; acc.z += xs * wv.z; acc.w += xs * wv.w;
        }
        cred[kg * 8 + of4] = acc;
        __syncthreads();
        if (t < 8) {
            float4 r = cred[t];
            #pragma unroll
            for (int j = 1; j < 32; j++) {
                float4 b = cred[j * 8 + t];
                r.x += b.x; r.y += b.y; r.z += b.z; r.w += b.w;
            }
            float4 bb = __ldg((const float4*)fc2_b + w * 8 + t);
            r.x += bb.x; r.y += bb.y; r.z += bb.z; r.w += bb.w;
            g_y2v[w * 8 + t] = r;
            float s = r.x + r.y + r.z + r.w;
            float q = r.x * r.x + r.y * r.y + r.z * r.z + r.w * r.w;
            #pragma unroll
            for (int off = 4; off > 0; off >>= 1) {
                s += __shfl_down_sync(0xffu, s, off, 8);
                q += __shfl_down_sync(0xffu, q, off, 8);
            }
            if (t == 0) { g_part[1][w][0] = s; g_part[1][w][1] = q; }
        }
    }
    wbar(w == 0);          // workers 1..7 arrive and exit
    if (w != 0) return;

    // ---- block 0: LN2 + relu, mu head, sigmoid, out, cleanup ---------------
    {
        if (t == 0) {
            float s = 0.f, q = 0.f;
            #pragma unroll
            for (int j = 0; j < NW; j++) { s += g_part[1][j][0]; q += g_part[1][j][1]; }
            float mean = s * (1.0f / 256.0f);
            float var  = q * (1.0f / 256.0f) - mean * mean;
            misc[2] = mean; misc[3] = rsqrtf(var + 1e-5f);
        }
        __syncthreads();
        if (t < 64) {
            float mean = misc[2], is = misc[3];
            float4 y  = g_y2v[t];
            float4 lw = __ldg((const float4*)ln2_w + t);
            float4 lb = __ldg((const float4*)ln2_b + t);
            float4 r;
            r.x = fmaxf((y.x - mean) * is * lw.x + lb.x, 0.f);
            r.y = fmaxf((y.y - mean) * is * lw.y + lb.y, 0.f);
            r.z = fmaxf((y.z - mean) * is * lw.z + lb.z, 0.f);
            r.w = fmaxf((y.w - mean) * is * lw.w + lb.w, 0.f);
            ((float4*)xv)[t] = r;
        }
        __syncthreads();

        float acc = 0.f;
        #pragma unroll
        for (int k = lane; k < 256; k += 32) acc += xv[k] * __ldg(&mu_w[k * 8 + wp]);
        #pragma unroll
        for (int off = 16; off > 0; off >>= 1)
            acc += __shfl_down_sync(0xffffffffu, acc, off);
        if (lane == 0) {
            float z = acc + mu_b[wp];
            out[wp] = 1.0f / (1.0f + expf(-z));
        }
        __syncthreads();

        // cleanup: reset only touched global state (replay-clean)
        int nc = min(g_nsrc, MAX_SRC);
        for (int m = t; m < nc; m += 256) {
            int s = g_srcs[m];
            g_bitmap[s >> 5] = 0;
            g_deg[s] = 0;
        }
        if (t == 0) {
            g_deg[agent] = 0;
            g_nsrc = 0;
        }
    }
}

// ---------------------------------------------------------------------------
extern "C" void kernel_launch(void* const* d_in, const int* in_sizes, int n_in,
                              void* d_out, int out_size) {
    const float* state  = (const float*)d_in[0];
    const void*  edges  = d_in[1];
    const void*  agent  = d_in[2];
    const float* conv_w = (const float*)d_in[3];
    const float* conv_b = (const float*)d_in[4];
    const float* fc1_w  = (const float*)d_in[5];
    const float* fc1_b  = (const float*)d_in[6];
    const float* ln1_w  = (const float*)d_in[7];
    const float* ln1_b  = (const float*)d_in[8];
    const float* fc2_w  = (const float*)d_in[9];
    const float* fc2_b  = (const float*)d_in[10];
    const float* ln2_w  = (const float*)d_in[11];
    const float* ln2_b  = (const float*)d_in[12];
    const float* mu_w   = (const float*)d_in[13];
    const float* mu_b   = (const float*)d_in[14];

    long long E = (long long)in_sizes[1] / 2;

    int dev = 0, sms = 0;
    cudaGetDevice(&dev);
    cudaDeviceGetAttribute(&sms, cudaDevAttrMultiProcessorCount, dev);
    if (sms < NW) sms = NW;

    k_fused<<<sms, 256>>>(state, edges, agent, conv_w, conv_b,
                          fc1_w, fc1_b, ln1_w, ln1_b,
                          fc2_w, fc2_b, ln2_w, ln2_b,
                          mu_w, mu_b, (float*)d_out, E);
}

// round 9
// speedup vs baseline: 1.5195x; 1.0182x over previous
#include <cuda_runtime.h>
#include <math.h>

#define N_NODES 50000
#define D_IN 128
#define MAX_SRC 2048
#define SH_SRC 1024
#define BM_WORDS 1568          // ceil(50000/32)
#define NW 8                   // worker blocks for distributed MLP tail
#define STASH_CAP 22528        // u16 entries (44KB)

// persistent device scratch (zero-initialized; kernel leaves it zeroed)
__device__ int g_deg[N_NODES];
__device__ unsigned g_bitmap[BM_WORDS];
__device__ int g_srcs[MAX_SRC];
__device__ int g_nsrc;
__device__ unsigned g_arrive;
__device__ volatile unsigned g_epoch;
__device__ unsigned g_wb_arrive;
__device__ volatile unsigned g_wb_epoch;
// inter-worker staging (fully overwritten each replay)
__device__ float4 g_y1v[64];
__device__ float4 g_y2v[64];
__device__ float g_part[2][NW][2];

// ---------------------------------------------------------------------------
// grid barrier; wait_=false -> arrive only (callers that exit right after)
__device__ __forceinline__ void gbar(bool wait_) {
    __syncthreads();
    if (threadIdx.x == 0) {
        __threadfence();
        unsigned e = g_epoch;
        if (atomicAdd(&g_arrive, 1u) == gridDim.x - 1) {
            g_arrive = 0;
            __threadfence();
            g_epoch = e + 1;
        } else if (wait_) {
            while (g_epoch == e) __nanosleep(20);
        }
        __threadfence();
    }
    __syncthreads();
}

// 8-worker mini-barrier; wait_=false -> arrive only
__device__ __forceinline__ void wbar(bool wait_) {
    __syncthreads();
    if (threadIdx.x == 0) {
        __threadfence();
        unsigned e = g_wb_epoch;
        if (atomicAdd(&g_wb_arrive, 1u) == NW - 1) {
            g_wb_arrive = 0;
            __threadfence();
            g_wb_epoch = e + 1;
        } else if (wait_) {
            while (g_wb_epoch == e) __nanosleep(20);
        }
        __threadfence();
    }
    __syncthreads();
}

// src-hit handler (rare path)
__device__ __forceinline__ void note_src(int s) {
    int p = atomicAdd(&g_nsrc, 1);
    if (p < MAX_SRC) {
        g_srcs[p] = s;
        atomicOr(&g_bitmap[s >> 5], 1u << (s & 31));
    }
}

// ---------------------------------------------------------------------------
__global__ void __launch_bounds__(256, 1) k_fused(
    const float* __restrict__ state,
    const void*  __restrict__ edges,
    const void*  __restrict__ agent_ptr,
    const float* __restrict__ conv_w, const float* __restrict__ conv_b,
    const float* __restrict__ fc1_w,  const float* __restrict__ fc1_b,
    const float* __restrict__ ln1_w,  const float* __restrict__ ln1_b,
    const float* __restrict__ fc2_w,  const float* __restrict__ fc2_b,
    const float* __restrict__ ln2_w,  const float* __restrict__ ln2_b,
    const float* __restrict__ mu_w,   const float* __restrict__ mu_b,
    float* __restrict__ out, long long E)
{
    __shared__ __align__(16) unsigned char sbuf[STASH_CAP * 2];
    unsigned short* stash = (unsigned short*)sbuf;

    const int t = threadIdx.x;
    const int w = blockIdx.x;

    // ---- local decode: edge dtype + agent ---------------------------------
    int is64 = 1;
    {
        const int* wd = (const int*)edges;
        #pragma unroll
        for (int j = 0; j < 16; j++)
            if (wd[2 * j + 1] != 0) { is64 = 0; break; }
    }
    int agent = *(const int*)agent_ptr;
    if (agent < 0 || agent >= N_NODES) agent = (int)(*(const float*)agent_ptr);

    // ---- P1: scan this block's dst chunk; stash u16; collect srcs+bitmap --
    long long chunk = (E + gridDim.x - 1) / gridDim.x;
    chunk = (chunk + 3) & ~3LL;
    const long long start = (long long)w * chunk;
    const long long end   = min(start + chunk, E);
    const int clen = (int)max(0LL, end - start);
    const bool fits = (chunk <= STASH_CAP);

    if (is64) {
        const long long* src = (const long long*)edges;
        const long long* dst = src + E;
        const bool vec = fits && ((((size_t)(dst + start)) & 15) == 0);
        if (vec) {
            const int vlim = clen & ~1;
            // 4 independent 16B loads in flight per thread per iteration
            for (int base = t * 2; base < vlim; base += 2048) {
                longlong2 v[4];
                #pragma unroll
                for (int q = 0; q < 4; q++) {
                    int j = base + q * 512;
                    if (j < vlim) v[q] = *(const longlong2*)(dst + start + j);
                }
                #pragma unroll
                for (int q = 0; q < 4; q++) {
                    int j = base + q * 512;
                    if (j >= vlim) continue;
                    unsigned pack = (unsigned)(unsigned short)v[q].x |
                                    ((unsigned)(unsigned short)v[q].y << 16);
                    *(unsigned*)(stash + j) = pack;
                    if ((int)v[q].x == agent) note_src((int)src[start + j]);
                    if ((int)v[q].y == agent) note_src((int)src[start + j + 1]);
                }
            }
            for (int k = vlim + t; k < clen; k += 256) {
                int d = (int)dst[start + k];
                stash[k] = (unsigned short)d;
                if (d == agent) note_src((int)src[start + k]);
            }
        } else {
            for (int j = t; j < clen; j += 256) {
                int d = (int)dst[start + j];
                if (fits) stash[j] = (unsigned short)d;
                if (d == agent) note_src((int)src[start + j]);
            }
        }
    } else {
        const int* src = (const int*)edges;
        const int* dst = src + E;
        const bool vec = fits && ((((size_t)(dst + start)) & 15) == 0);
        if (vec) {
            const int vlim = clen & ~3;
            for (int base = t * 4; base < vlim; base += 4096) {
                int4 v[4];
                #pragma unroll
                for (int q = 0; q < 4; q++) {
                    int j = base + q * 1024;
                    if (j < vlim) v[q] = *(const int4*)(dst + start + j);
                }
                #pragma unroll
                for (int q = 0; q < 4; q++) {
                    int j = base + q * 1024;
                    if (j >= vlim) continue;
                    *(unsigned*)(stash + j)     = (unsigned)(unsigned short)v[q].x |
                                                  ((unsigned)(unsigned short)v[q].y << 16);
                    *(unsigned*)(stash + j + 2) = (unsigned)(unsigned short)v[q].z |
                                                  ((unsigned)(unsigned short)v[q].w << 16);
                    if (v[q].x == agent) note_src(src[start + j]);
                    if (v[q].y == agent) note_src(src[start + j + 1]);
                    if (v[q].z == agent) note_src(src[start + j + 2]);
                    if (v[q].w == agent) note_src(src[start + j + 3]);
                }
            }
            for (int k = vlim + t; k < clen; k += 256) {
                int d = dst[start + k];
                stash[k] = (unsigned short)d;
                if (d == agent) note_src(src[start + k]);
            }
        } else {
            for (int j = t; j < clen; j += 256) {
                int d = dst[start + j];
                if (fits) stash[j] = (unsigned short)d;
                if (d == agent) note_src(src[start + j]);
            }
        }
    }
    gbar(true);

    // ---- P2: filtered degree histogram ------------------------------------
    if (fits) {
        for (int j = t; j < clen; j += 256) {
            int d = stash[j];
            unsigned wd = __ldg(&g_bitmap[d >> 5]);
            if ((wd >> (d & 31)) & 1u) atomicAdd(&g_deg[d], 1);
        }
    } else {
        const long long* dst64 = (const long long*)edges + E;
        const int*       dst32 = (const int*)edges + E;
        for (int j = t; j < clen; j += 256) {
            int d = is64 ? (int)dst64[start + j] : dst32[start + j];
            unsigned wd = __ldg(&g_bitmap[d >> 5]);
            if ((wd >> (d & 31)) & 1u) atomicAdd(&g_deg[d], 1);
        }
    }
    gbar(w < NW);          // non-workers arrive and exit

    if (w >= NW) return;

    // ================= distributed MLP on blocks 0..7 ======================
    float*  agg   = (float*)(sbuf);                 // 128 f   [0,512)
    float*  xv    = (float*)(sbuf + 512);           // 256 f   [512,1536)
    float4* sred  = (float4*)(sbuf + 1536);         // 8*32 f4 [1536,5632)
    float4* cred  = (float4*)(sbuf + 5632);         // 4*64 f4 [5632,9728)
    float*  misc  = (float*)(sbuf + 9728);          // few floats
    int*    ssrc  = (int*)(sbuf + 10240);           // 1024 i
    float*  snorm = (float*)(sbuf + 14336);         // 1024 f

    const int lane = t & 31, wp = t >> 5;
    const int n = min(g_nsrc, SH_SRC);
    const float dinv_a = rsqrtf((float)(g_nsrc + 1));

    __syncthreads();   // stash -> MLP scratch reuse
    for (int m = t; m < n; m += 256) {
        int s = g_srcs[m];
        ssrc[m]  = s;
        snorm[m] = rsqrtf((float)(g_deg[s] + 1)) * dinv_a;
    }
    __syncthreads();

    // ---- agg (redundant on each worker): warp wp takes m = wp, wp+8, ...
    {
        float4 a = make_float4(0.f, 0.f, 0.f, 0.f);
        for (int m = wp; m < n; m += 8) {
            const float4* row = (const float4*)(state + (size_t)ssrc[m] * D_IN);
            float4 v = __ldg(&row[lane]);
            float nm = snorm[m];
            a.x += nm * v.x; a.y += nm * v.y; a.z += nm * v.z; a.w += nm * v.w;
        }
        sred[wp * 32 + lane] = a;
        __syncthreads();
        if (t < 32) {
            float4 s4 = sred[t];
            #pragma unroll
            for (int j = 1; j < 8; j++) {
                float4 b = sred[j * 32 + t];
                s4.x += b.x; s4.y += b.y; s4.z += b.z; s4.w += b.w;
            }
            const float4* arow = (const float4*)(state + (size_t)agent * D_IN);
            float4 av = __ldg(&arow[t]);
            float c = dinv_a * dinv_a;
            s4.x += c * av.x; s4.y += c * av.y; s4.z += c * av.z; s4.w += c * av.w;
            ((float4*)agg)[t] = s4;
        }
        __syncthreads();
    }

    const int og = t & 63, sl = t >> 6;
    const int of4 = t & 7, kg = t >> 3;

    // ---- conv GEMV full (redundant per worker), 4-wide staging -------------
    {
        float4 acc = make_float4(0.f, 0.f, 0.f, 0.f);
        const int kb = sl * 32;
        #pragma unroll
        for (int kk = 0; kk < 32; kk += 4) {
            float4 wv[4];
            #pragma unroll
            for (int j = 0; j < 4; j++)
                wv[j] = __ldg((const float4*)(conv_w + (size_t)(kb + kk + j) * 256) + og);
            #pragma unroll
            for (int j = 0; j < 4; j++) {
                float xs = agg[kb + kk + j];
                acc.x += xs * wv[j].x; acc.y += xs * wv[j].y;
                acc.z += xs * wv[j].z; acc.w += xs * wv[j].w;
            }
        }
        cred[sl * 64 + og] = acc;
        __syncthreads();
        if (t < 64) {
            float4 r = cred[t], b1 = cred[64 + t], b2 = cred[128 + t], b3 = cred[192 + t];
            r.x += b1.x + b2.x + b3.x; r.y += b1.y + b2.y + b3.y;
            r.z += b1.z + b2.z + b3.z; r.w += b1.w + b2.w + b3.w;
            float4 bb = __ldg((const float4*)conv_b + t);
            r.x = fmaxf(r.x + bb.x, 0.f); r.y = fmaxf(r.y + bb.y, 0.f);
            r.z = fmaxf(r.z + bb.z, 0.f); r.w = fmaxf(r.w + bb.w, 0.f);
            ((float4*)xv)[t] = r;
        }
        __syncthreads();
    }

    // ---- fc1 slice (32 outputs at columns w*32..w*32+31) -------------------
    {
        float4 acc = make_float4(0.f, 0.f, 0.f, 0.f);
        #pragma unroll
        for (int i = 0; i < 8; i++) {
            int k = kg * 8 + i;
            float xs = xv[k];
            float4 wv = __ldg((const float4*)(fc1_w + (size_t)k * 256 + w * 32) + of4);
            acc.x += xs * wv.x; acc.y += xs * wv.y; acc.z += xs * wv.z; acc.w += xs * wv.w;
        }
        cred[kg * 8 + of4] = acc;
        __syncthreads();
        if (t < 8) {
            float4 r = cred[t];
            #pragma unroll
            for (int j = 1; j < 32; j++) {
                float4 b = cred[j * 8 + t];
                r.x += b.x; r.y += b.y; r.z += b.z; r.w += b.w;
            }
            float4 bb = __ldg((const float4*)fc1_b + w * 8 + t);
            r.x += bb.x; r.y += bb.y; r.z += bb.z; r.w += bb.w;
            g_y1v[w * 8 + t] = r;
            float s = r.x + r.y + r.z + r.w;
            float q = r.x * r.x + r.y * r.y + r.z * r.z + r.w * r.w;
            #pragma unroll
            for (int off = 4; off > 0; off >>= 1) {
                s += __shfl_down_sync(0xffu, s, off, 8);
                q += __shfl_down_sync(0xffu, q, off, 8);
            }
            if (t == 0) { g_part[0][w][0] = s; g_part[0][w][1] = q; }
        }
    }
    wbar(true);

    // ---- LN1 + relu (redundant), fc2 slice ---------------------------------
    {
        if (t == 0) {
            float s = 0.f, q = 0.f;
            #pragma unroll
            for (int j = 0; j < NW; j++) { s += g_part[0][j][0]; q += g_part[0][j][1]; }
            float mean = s * (1.0f / 256.0f);
            float var  = q * (1.0f / 256.0f) - mean * mean;
            misc[0] = mean; misc[1] = rsqrtf(var + 1e-5f);
        }
        __syncthreads();
        if (t < 64) {
            float mean = misc[0], is = misc[1];
            float4 y  = g_y1v[t];
            float4 lw = __ldg((const float4*)ln1_w + t);
            float4 lb = __ldg((const float4*)ln1_b + t);
            float4 r;
            r.x = fmaxf((y.x - mean) * is * lw.x + lb.x, 0.f);
            r.y = fmaxf((y.y - mean) * is * lw.y + lb.y, 0.f);
            r.z = fmaxf((y.z - mean) * is * lw.z + lb.z, 0.f);
            r.w = fmaxf((y.w - mean) * is * lw.w + lb.w, 0.f);
            ((float4*)xv)[t] = r;
        }
        __syncthreads();

        float4 acc = make_float4(0.f, 0.f, 0.f, 0.f);
        #pragma unroll
        for (int i = 0; i < 8; i++) {
            int k = kg * 8 + i;
            float xs = xv[k];
            float4 wv = __ldg((const float4*)(fc2_w + (size_t)k * 256 + w * 32) + of4);
            acc.x += xs * wv.x; acc.y += xs * wv.y; acc.z += xs * wv.z; acc.w += xs * wv.w;
        }
        cred[kg * 8 + of4] = acc;
        __syncthreads();
        if (t < 8) {
            float4 r = cred[t];
            #pragma unroll
            for (int j = 1; j < 32; j++) {
                float4 b = cred[j * 8 + t];
                r.x += b.x; r.y += b.y; r.z += b.z; r.w += b.w;
            }
            float4 bb = __ldg((const float4*)fc2_b + w * 8 + t);
            r.x += bb.x; r.y += bb.y; r.z += bb.z; r.w += bb.w;
            g_y2v[w * 8 + t] = r;
            float s = r.x + r.y + r.z + r.w;
            float q = r.x * r.x + r.y * r.y + r.z * r.z + r.w * r.w;
            #pragma unroll
            for (int off = 4; off > 0; off >>= 1) {
                s += __shfl_down_sync(0xffu, s, off, 8);
                q += __shfl_down_sync(0xffu, q, off, 8);
            }
            if (t == 0) { g_part[1][w][0] = s; g_part[1][w][1] = q; }
        }
    }
    wbar(w == 0);          // workers 1..7 arrive and exit
    if (w != 0) return;

    // ---- block 0: LN2 + relu, mu head, sigmoid, out, cleanup ---------------
    {
        if (t == 0) {
            float s = 0.f, q = 0.f;
            #pragma unroll
            for (int j = 0; j < NW; j++) { s += g_part[1][j][0]; q += g_part[1][j][1]; }
            float mean = s * (1.0f / 256.0f);
            float var  = q * (1.0f / 256.0f) - mean * mean;
            misc[2] = mean; misc[3] = rsqrtf(var + 1e-5f);
        }
        __syncthreads();
        if (t < 64) {
            float mean = misc[2], is = misc[3];
            float4 y  = g_y2v[t];
            float4 lw = __ldg((const float4*)ln2_w + t);
            float4 lb = __ldg((const float4*)ln2_b + t);
            float4 r;
            r.x = fmaxf((y.x - mean) * is * lw.x + lb.x, 0.f);
            r.y = fmaxf((y.y - mean) * is * lw.y + lb.y, 0.f);
            r.z = fmaxf((y.z - mean) * is * lw.z + lb.z, 0.f);
            r.w = fmaxf((y.w - mean) * is * lw.w + lb.w, 0.f);
            ((float4*)xv)[t] = r;
        }
        __syncthreads();

        float acc = 0.f;
        #pragma unroll
        for (int k = lane; k < 256; k += 32) acc += xv[k] * __ldg(&mu_w[k * 8 + wp]);
        #pragma unroll
        for (int off = 16; off > 0; off >>= 1)
            acc += __shfl_down_sync(0xffffffffu, acc, off);
        if (lane == 0) {
            float z = acc + mu_b[wp];
            out[wp] = 1.0f / (1.0f + expf(-z));
        }
        __syncthreads();

        // cleanup: reset only touched global state (replay-clean)
        int nc = min(g_nsrc, MAX_SRC);
        for (int m = t; m < nc; m += 256) {
            int s = g_srcs[m];
            g_bitmap[s >> 5] = 0;
            g_deg[s] = 0;
        }
        if (t == 0) {
            g_deg[agent] = 0;
            g_nsrc = 0;
        }
    }
}

// ---------------------------------------------------------------------------
extern "C" void kernel_launch(void* const* d_in, const int* in_sizes, int n_in,
                              void* d_out, int out_size) {
    const float* state  = (const float*)d_in[0];
    const void*  edges  = d_in[1];
    const void*  agent  = d_in[2];
    const float* conv_w = (const float*)d_in[3];
    const float* conv_b = (const float*)d_in[4];
    const float* fc1_w  = (const float*)d_in[5];
    const float* fc1_b  = (const float*)d_in[6];
    const float* ln1_w  = (const float*)d_in[7];
    const float* ln1_b  = (const float*)d_in[8];
    const float* fc2_w  = (const float*)d_in[9];
    const float* fc2_b  = (const float*)d_in[10];
    const float* ln2_w  = (const float*)d_in[11];
    const float* ln2_b  = (const float*)d_in[12];
    const float* mu_w   = (const float*)d_in[13];
    const float* mu_b   = (const float*)d_in[14];

    long long E = (long long)in_sizes[1] / 2;

    int dev = 0, sms = 0;
    cudaGetDevice(&dev);
    cudaDeviceGetAttribute(&sms, cudaDevAttrMultiProcessorCount, dev);
    if (sms < NW) sms = NW;

    k_fused<<<sms, 256>>>(state, edges, agent, conv_w, conv_b,
                          fc1_w, fc1_b, ln1_w, ln1_b,
                          fc2_w, fc2_b, ln2_w, ln2_b,
                          mu_w, mu_b, (float*)d_out, E);
}